// round 2
// baseline (speedup 1.0000x reference)
#include <cuda_runtime.h>
#include <cuda_bf16.h>
#include <stdint.h>

#define N_NODES 50000
#define N_EDGES 600000
#define D 128
#define EPS 1e-5f

// ---------------- scratch (device globals; no allocations allowed) ----------
__device__ float g_hn[N_NODES * D];      // layernormed features
__device__ float g_msg[N_NODES * D];     // aggregated message * inv_sqrt_in
__device__ int   g_deg_in[N_NODES];
__device__ int   g_deg_out[N_NODES];
__device__ float g_inv_in[N_NODES];
__device__ float g_inv_out[N_NODES];
__device__ int   g_rowstart[N_NODES + 1];
__device__ int   g_cursor[N_NODES];
__device__ int   g_csr_src[N_EDGES];

// ---------------- K0: zero counters (graph replay must be deterministic) ----
__global__ void k_zero() {
    int i = blockIdx.x * blockDim.x + threadIdx.x;
    if (i < N_NODES) {
        g_deg_in[i] = 0;
        g_deg_out[i] = 0;
        g_cursor[i] = 0;
    }
}

// ---------------- K1: degree counts -----------------------------------------
__global__ void k_count(const int* __restrict__ src,
                        const int* __restrict__ dst) {
    int i = blockIdx.x * blockDim.x + threadIdx.x;
    if (i < N_EDGES) {
        atomicAdd(&g_deg_out[src[i]], 1);
        atomicAdd(&g_deg_in[dst[i]], 1);
    }
}

// ---------------- K2: LayerNorm (warp per row) + inv-sqrt degrees -----------
__global__ void k_layernorm(const float* __restrict__ h,
                            const float* __restrict__ gamma,
                            const float* __restrict__ beta) {
    int warp = (blockIdx.x * blockDim.x + threadIdx.x) >> 5;
    int lane = threadIdx.x & 31;
    if (warp >= N_NODES) return;

    float4 v = ((const float4*)h)[warp * 32 + lane];
    float s  = v.x + v.y + v.z + v.w;
    float sq = v.x * v.x + v.y * v.y + v.z * v.z + v.w * v.w;
    #pragma unroll
    for (int off = 16; off > 0; off >>= 1) {
        s  += __shfl_xor_sync(0xFFFFFFFF, s,  off);
        sq += __shfl_xor_sync(0xFFFFFFFF, sq, off);
    }
    float mu  = s * (1.0f / D);
    float var = sq * (1.0f / D) - mu * mu;
    float rs  = rsqrtf(var + EPS);

    float4 g = ((const float4*)gamma)[lane];
    float4 b = ((const float4*)beta)[lane];
    float4 o;
    o.x = (v.x - mu) * rs * g.x + b.x;
    o.y = (v.y - mu) * rs * g.y + b.y;
    o.z = (v.z - mu) * rs * g.z + b.z;
    o.w = (v.w - mu) * rs * g.w + b.w;
    ((float4*)g_hn)[warp * 32 + lane] = o;

    if (lane == 0) {
        int din  = g_deg_in[warp];
        int dout = g_deg_out[warp];
        g_inv_in[warp]  = rsqrtf((float)(din  < 1 ? 1 : din));
        g_inv_out[warp] = rsqrtf((float)(dout < 1 ? 1 : dout));
    }
}

// ---------------- K3: exclusive prefix scan of deg_in -> rowstart -----------
#define SCAN_T 1024
#define CHUNK ((N_NODES + SCAN_T - 1) / SCAN_T)   // 49
__global__ void k_scan() {
    __shared__ int sh[SCAN_T];
    int t = threadIdx.x;
    int start = t * CHUNK;
    int sum = 0;
    #pragma unroll 4
    for (int i = 0; i < CHUNK; i++) {
        int idx = start + i;
        if (idx < N_NODES) sum += g_deg_in[idx];
    }
    sh[t] = sum;
    __syncthreads();
    // Kogge-Stone inclusive scan
    for (int off = 1; off < SCAN_T; off <<= 1) {
        int v = (t >= off) ? sh[t - off] : 0;
        __syncthreads();
        sh[t] += v;
        __syncthreads();
    }
    int run = (t == 0) ? 0 : sh[t - 1];
    for (int i = 0; i < CHUNK; i++) {
        int idx = start + i;
        if (idx < N_NODES) {
            g_rowstart[idx] = run;
            run += g_deg_in[idx];
        }
    }
    if (t == 0) g_rowstart[N_NODES] = sh[SCAN_T - 1];
}

// ---------------- K4: scatter edges into CSR-by-destination ------------------
__global__ void k_fill_csr(const int* __restrict__ src,
                           const int* __restrict__ dst) {
    int i = blockIdx.x * blockDim.x + threadIdx.x;
    if (i < N_EDGES) {
        int d = dst[i];
        int pos = atomicAdd(&g_cursor[d], 1);
        g_csr_src[g_rowstart[d] + pos] = src[i];
    }
}

// ---------------- K5: aggregation (warp per destination node) ----------------
__global__ void k_aggregate() {
    int warp = (blockIdx.x * blockDim.x + threadIdx.x) >> 5;
    int lane = threadIdx.x & 31;
    if (warp >= N_NODES) return;

    int e0 = g_rowstart[warp];
    int e1 = g_rowstart[warp + 1];
    float4 acc = make_float4(0.f, 0.f, 0.f, 0.f);
    for (int e = e0; e < e1; e++) {
        int s = g_csr_src[e];
        float w = g_inv_out[s];                       // broadcast within warp
        float4 v = ((const float4*)g_hn)[s * 32 + lane];
        acc.x += v.x * w;
        acc.y += v.y * w;
        acc.z += v.z * w;
        acc.w += v.w * w;
    }
    float wi = g_inv_in[warp];
    acc.x *= wi; acc.y *= wi; acc.z *= wi; acc.w *= wi;
    ((float4*)g_msg)[warp * 32 + lane] = acc;
}

// ---------------- K6: GEMM  out = [hn | msg] @ W^T + b -----------------------
// BM=64 rows, BN=128 cols (all outputs), BK=32, 256 threads, 8x4 per thread.
#define BM 64
#define BN 128
#define BK 32
__global__ __launch_bounds__(256)
void k_gemm(const float* __restrict__ W,    // [128][256] row-major
            const float* __restrict__ bias, // [128]
            float* __restrict__ out) {      // [N][128]
    __shared__ float As[BK][BM + 4];
    __shared__ float Ws[BK][BN + 4];

    int tid = threadIdx.x;
    int rowBase = blockIdx.x * BM;
    int tidN = tid & 31;   // 32 col-groups of 4
    int tidM = tid >> 5;   // 8 row-groups of 8

    float acc[8][4];
    #pragma unroll
    for (int i = 0; i < 8; i++)
        #pragma unroll
        for (int j = 0; j < 4; j++) acc[i][j] = 0.f;

    #pragma unroll
    for (int kk = 0; kk < 2 * D; kk += BK) {
        const float* Asrc = (kk < D) ? g_hn : g_msg;
        int kOff = kk & (D - 1);

        // stage A tile (64 x 32), transposed into As[k][row]
        #pragma unroll
        for (int it = 0; it < 2; it++) {
            int id = tid + it * 256;        // 0..511 float4 slots
            int r  = id >> 3;               // 0..63
            int c4 = id & 7;                // 0..7
            int gr = rowBase + r;
            float4 v = make_float4(0.f, 0.f, 0.f, 0.f);
            if (gr < N_NODES)
                v = *(const float4*)&Asrc[gr * D + kOff + c4 * 4];
            As[c4 * 4 + 0][r] = v.x;
            As[c4 * 4 + 1][r] = v.y;
            As[c4 * 4 + 2][r] = v.z;
            As[c4 * 4 + 3][r] = v.w;
        }
        // stage W tile (128 x 32) transposed into Ws[k][j]
        #pragma unroll
        for (int it = 0; it < 4; it++) {
            int id = tid + it * 256;        // 0..1023 float4 slots
            int j  = id >> 3;               // 0..127
            int c4 = id & 7;
            float4 v = *(const float4*)&W[j * 256 + kk + c4 * 4];
            Ws[c4 * 4 + 0][j] = v.x;
            Ws[c4 * 4 + 1][j] = v.y;
            Ws[c4 * 4 + 2][j] = v.z;
            Ws[c4 * 4 + 3][j] = v.w;
        }
        __syncthreads();

        #pragma unroll
        for (int k = 0; k < BK; k++) {
            float4 a0 = *(const float4*)&As[k][tidM * 8];
            float4 a1 = *(const float4*)&As[k][tidM * 8 + 4];
            float4 wv = *(const float4*)&Ws[k][tidN * 4];
            float a[8] = {a0.x, a0.y, a0.z, a0.w, a1.x, a1.y, a1.z, a1.w};
            float w[4] = {wv.x, wv.y, wv.z, wv.w};
            #pragma unroll
            for (int i = 0; i < 8; i++)
                #pragma unroll
                for (int j = 0; j < 4; j++)
                    acc[i][j] += a[i] * w[j];
        }
        __syncthreads();
    }

    // epilogue: add bias, store float4 per row-group
    float4 bv = *(const float4*)&bias[tidN * 4];
    #pragma unroll
    for (int i = 0; i < 8; i++) {
        int gr = rowBase + tidM * 8 + i;
        if (gr < N_NODES) {
            float4 o;
            o.x = acc[i][0] + bv.x;
            o.y = acc[i][1] + bv.y;
            o.z = acc[i][2] + bv.z;
            o.w = acc[i][3] + bv.w;
            *(float4*)&out[gr * D + tidN * 4] = o;
        }
    }
}

// ---------------- launcher ---------------------------------------------------
extern "C" void kernel_launch(void* const* d_in, const int* in_sizes, int n_in,
                              void* d_out, int out_size) {
    const float* h     = (const float*)d_in[0];
    const int*   ei    = (const int*)d_in[1];   // [2][E] int32 (JAX x64 disabled)
    const float* gamma = (const float*)d_in[2];
    const float* beta  = (const float*)d_in[3];
    const float* W     = (const float*)d_in[4];
    const float* bias  = (const float*)d_in[5];
    float*       out   = (float*)d_out;

    const int* src = ei;
    const int* dst = ei + N_EDGES;

    k_zero<<<(N_NODES + 255) / 256, 256>>>();
    k_count<<<(N_EDGES + 255) / 256, 256>>>(src, dst);
    k_layernorm<<<(N_NODES * 32 + 255) / 256, 256>>>(h, gamma, beta);
    k_scan<<<1, SCAN_T>>>();
    k_fill_csr<<<(N_EDGES + 255) / 256, 256>>>(src, dst);
    k_aggregate<<<(N_NODES * 32 + 255) / 256, 256>>>();
    k_gemm<<<(N_NODES + BM - 1) / BM, 256>>>(W, bias, out);
}

// round 4
// speedup vs baseline: 1.9272x; 1.9272x over previous
#include <cuda_runtime.h>
#include <cuda_bf16.h>
#include <stdint.h>

#define N_NODES 50000
#define N_EDGES 600000
#define D 128
#define EPS 1e-5f
#define SCAN_BLOCKS 49   // ceil(50000/1024)

// ---------------- scratch (device globals; no allocations allowed) ----------
__device__ float g_hn[N_NODES * D];      // layernormed features
__device__ float g_msg[N_NODES * D];     // aggregated message * inv_sqrt_in
__device__ int   g_deg_in[N_NODES];
__device__ int   g_deg_out[N_NODES];
__device__ float g_inv_in[N_NODES];
__device__ float g_inv_out[N_NODES];
__device__ int   g_rowstart[N_NODES];    // block-local exclusive scan of deg_in
__device__ int   g_blocksum[SCAN_BLOCKS];
__device__ int   g_blockoff[SCAN_BLOCKS];
__device__ int   g_cursor[N_NODES];
__device__ int   g_csr_src[N_EDGES];

__device__ __forceinline__ int row_begin(int w) {
    return g_rowstart[w] + g_blockoff[w >> 10];
}

// ---------------- K0: zero counters -----------------------------------------
__global__ void k_zero() {
    int i = blockIdx.x * blockDim.x + threadIdx.x;
    if (i < N_NODES) {
        g_deg_in[i] = 0;
        g_deg_out[i] = 0;
        g_cursor[i] = 0;
    }
}

// ---------------- K1: degree counts -----------------------------------------
__global__ void k_count(const int* __restrict__ src,
                        const int* __restrict__ dst) {
    int i = blockIdx.x * blockDim.x + threadIdx.x;
    if (i < N_EDGES) {
        atomicAdd(&g_deg_out[src[i]], 1);
        atomicAdd(&g_deg_in[dst[i]], 1);
    }
}

// ---------------- K2: LayerNorm (warp per row) + inv-sqrt degrees -----------
__global__ void k_layernorm(const float* __restrict__ h,
                            const float* __restrict__ gamma,
                            const float* __restrict__ beta) {
    int warp = (blockIdx.x * blockDim.x + threadIdx.x) >> 5;
    int lane = threadIdx.x & 31;
    if (warp >= N_NODES) return;

    float4 v = ((const float4*)h)[warp * 32 + lane];
    float s  = v.x + v.y + v.z + v.w;
    float sq = v.x * v.x + v.y * v.y + v.z * v.z + v.w * v.w;
    #pragma unroll
    for (int off = 16; off > 0; off >>= 1) {
        s  += __shfl_xor_sync(0xFFFFFFFF, s,  off);
        sq += __shfl_xor_sync(0xFFFFFFFF, sq, off);
    }
    float mu  = s * (1.0f / D);
    float var = sq * (1.0f / D) - mu * mu;
    float rs  = rsqrtf(var + EPS);

    float4 g = ((const float4*)gamma)[lane];
    float4 b = ((const float4*)beta)[lane];
    float4 o;
    o.x = (v.x - mu) * rs * g.x + b.x;
    o.y = (v.y - mu) * rs * g.y + b.y;
    o.z = (v.z - mu) * rs * g.z + b.z;
    o.w = (v.w - mu) * rs * g.w + b.w;
    ((float4*)g_hn)[warp * 32 + lane] = o;

    if (lane == 0) {
        int din  = g_deg_in[warp];
        int dout = g_deg_out[warp];
        g_inv_in[warp]  = rsqrtf((float)(din  < 1 ? 1 : din));
        g_inv_out[warp] = rsqrtf((float)(dout < 1 ? 1 : dout));
    }
}

// ---------------- K3a: per-block exclusive scan of deg_in -------------------
__global__ __launch_bounds__(1024)
void k_scan_local() {
    __shared__ int warp_sums[32];
    int t = threadIdx.x;
    int i = blockIdx.x * 1024 + t;
    int lane = t & 31;
    int wid = t >> 5;

    int v = (i < N_NODES) ? g_deg_in[i] : 0;
    int incl = v;
    #pragma unroll
    for (int off = 1; off < 32; off <<= 1) {
        int n = __shfl_up_sync(0xFFFFFFFF, incl, off);
        if (lane >= off) incl += n;
    }
    if (lane == 31) warp_sums[wid] = incl;
    __syncthreads();
    if (wid == 0) {
        int ws = warp_sums[lane];
        int wi = ws;
        #pragma unroll
        for (int off = 1; off < 32; off <<= 1) {
            int n = __shfl_up_sync(0xFFFFFFFF, wi, off);
            if (lane >= off) wi += n;
        }
        warp_sums[lane] = wi - ws;   // exclusive warp offset
        if (lane == 31) g_blocksum[blockIdx.x] = wi;
    }
    __syncthreads();
    if (i < N_NODES)
        g_rowstart[i] = incl - v + warp_sums[wid];
}

// ---------------- K3b: scan the 49 block sums -> blockoff -------------------
__global__ void k_scan_block() {
    __shared__ int sh[64];
    int t = threadIdx.x;
    int v = (t < SCAN_BLOCKS) ? g_blocksum[t] : 0;
    sh[t] = v;
    __syncthreads();
    #pragma unroll
    for (int off = 1; off < 64; off <<= 1) {
        int x = (t >= off) ? sh[t - off] : 0;
        __syncthreads();
        sh[t] += x;
        __syncthreads();
    }
    if (t < SCAN_BLOCKS)
        g_blockoff[t] = sh[t] - v;   // exclusive
}

// ---------------- K4: scatter edges into CSR-by-destination ------------------
__global__ void k_fill_csr(const int* __restrict__ src,
                           const int* __restrict__ dst) {
    int i = blockIdx.x * blockDim.x + threadIdx.x;
    if (i < N_EDGES) {
        int d = dst[i];
        int pos = atomicAdd(&g_cursor[d], 1);
        g_csr_src[row_begin(d) + pos] = src[i];
    }
}

// ---------------- K5: aggregation (warp per destination node) ----------------
__global__ void k_aggregate() {
    int warp = (blockIdx.x * blockDim.x + threadIdx.x) >> 5;
    int lane = threadIdx.x & 31;
    if (warp >= N_NODES) return;

    int e0 = row_begin(warp);
    int e1 = (warp + 1 < N_NODES) ? row_begin(warp + 1) : N_EDGES;
    float4 acc = make_float4(0.f, 0.f, 0.f, 0.f);
    for (int e = e0; e < e1; e++) {
        int s = g_csr_src[e];
        float w = g_inv_out[s];
        float4 v = ((const float4*)g_hn)[s * 32 + lane];
        acc.x += v.x * w;
        acc.y += v.y * w;
        acc.z += v.z * w;
        acc.w += v.w * w;
    }
    float wi = g_inv_in[warp];
    acc.x *= wi; acc.y *= wi; acc.z *= wi; acc.w *= wi;
    ((float4*)g_msg)[warp * 32 + lane] = acc;
}

// ---------------- K6: TF32 tensor-core GEMM  out = [hn|msg] @ W^T + b --------
// BM=128, BN=128 (all cols), BK=32. 256 threads = 8 warps; warp w owns rows
// [w*16, w*16+16). mma.m16n8k8 tf32, 16 n-tiles per warp.
#define GBM 128
#define GBK 32

__device__ __forceinline__ uint32_t to_tf32(float x) {
    uint32_t r;
    asm("cvt.rna.tf32.f32 %0, %1;" : "=r"(r) : "f"(x));
    return r;
}

__global__ __launch_bounds__(256, 2)
void k_gemm(const float* __restrict__ W,    // [128][256] row-major
            const float* __restrict__ bias, // [128]
            float* __restrict__ out) {      // [N][128]
    __shared__ float As[GBM][36];          // stride 36: conflict-free frag reads
    __shared__ float Ws[GBK][132];         // k-major W tile

    int tid  = threadIdx.x;
    int warp = tid >> 5;
    int lane = tid & 31;
    int rowBase = blockIdx.x * GBM;

    float acc[16][4];
    #pragma unroll
    for (int j = 0; j < 16; j++)
        #pragma unroll
        for (int c = 0; c < 4; c++) acc[j][c] = 0.f;

    for (int kk = 0; kk < 2 * D; kk += GBK) {
        const float* Asrc = (kk < D) ? g_hn : g_msg;
        int kOff = kk & (D - 1);

        // stage A tile: 128 rows x 32 k (1024 float4 slots)
        #pragma unroll
        for (int it = 0; it < 4; it++) {
            int id = tid + it * 256;
            int r  = id >> 3;
            int c4 = id & 7;
            int gr = rowBase + r;
            float4 v = make_float4(0.f, 0.f, 0.f, 0.f);
            if (gr < N_NODES)
                v = *(const float4*)&Asrc[gr * D + kOff + c4 * 4];
            float4 t;
            t.x = __uint_as_float(to_tf32(v.x));
            t.y = __uint_as_float(to_tf32(v.y));
            t.z = __uint_as_float(to_tf32(v.z));
            t.w = __uint_as_float(to_tf32(v.w));
            *(float4*)&As[r][c4 * 4] = t;
        }
        // stage W tile transposed: Ws[k][n] = W[n][kk+k]
        #pragma unroll
        for (int it = 0; it < 4; it++) {
            int id = tid + it * 256;
            int n  = id >> 3;
            int c4 = id & 7;
            float4 v = *(const float4*)&W[n * 256 + kk + c4 * 4];
            Ws[c4 * 4 + 0][n] = __uint_as_float(to_tf32(v.x));
            Ws[c4 * 4 + 1][n] = __uint_as_float(to_tf32(v.y));
            Ws[c4 * 4 + 2][n] = __uint_as_float(to_tf32(v.z));
            Ws[c4 * 4 + 3][n] = __uint_as_float(to_tf32(v.w));
        }
        __syncthreads();

        int q = lane & 3;        // threadID_in_group
        int g = lane >> 2;       // groupID
        int r0 = warp * 16;
        #pragma unroll
        for (int k0 = 0; k0 < GBK; k0 += 8) {
            uint32_t a0 = __float_as_uint(As[r0 + g][k0 + q]);
            uint32_t a1 = __float_as_uint(As[r0 + g + 8][k0 + q]);
            uint32_t a2 = __float_as_uint(As[r0 + g][k0 + q + 4]);
            uint32_t a3 = __float_as_uint(As[r0 + g + 8][k0 + q + 4]);
            #pragma unroll
            for (int j = 0; j < 16; j++) {
                uint32_t b0 = __float_as_uint(Ws[k0 + q][j * 8 + g]);
                uint32_t b1 = __float_as_uint(Ws[k0 + q + 4][j * 8 + g]);
                asm volatile(
                    "mma.sync.aligned.m16n8k8.row.col.f32.tf32.tf32.f32 "
                    "{%0,%1,%2,%3}, {%4,%5,%6,%7}, {%8,%9}, {%0,%1,%2,%3};"
                    : "+f"(acc[j][0]), "+f"(acc[j][1]),
                      "+f"(acc[j][2]), "+f"(acc[j][3])
                    : "r"(a0), "r"(a1), "r"(a2), "r"(a3), "r"(b0), "r"(b1));
            }
        }
        __syncthreads();
    }

    // epilogue: bias + store (C frag: c0/c1 row g, c2/c3 row g+8; col 2q, 2q+1)
    int q = lane & 3;
    int g = lane >> 2;
    int row0 = rowBase + warp * 16 + g;
    int row1 = row0 + 8;
    #pragma unroll
    for (int j = 0; j < 16; j++) {
        int col = j * 8 + q * 2;
        float b0 = __ldg(&bias[col]);
        float b1 = __ldg(&bias[col + 1]);
        if (row0 < N_NODES) {
            float2 o = make_float2(acc[j][0] + b0, acc[j][1] + b1);
            *(float2*)&out[row0 * D + col] = o;
        }
        if (row1 < N_NODES) {
            float2 o = make_float2(acc[j][2] + b0, acc[j][3] + b1);
            *(float2*)&out[row1 * D + col] = o;
        }
    }
}

// ---------------- launcher ---------------------------------------------------
extern "C" void kernel_launch(void* const* d_in, const int* in_sizes, int n_in,
                              void* d_out, int out_size) {
    const float* h     = (const float*)d_in[0];
    const int*   ei    = (const int*)d_in[1];   // [2][E] int32
    const float* gamma = (const float*)d_in[2];
    const float* beta  = (const float*)d_in[3];
    const float* W     = (const float*)d_in[4];
    const float* bias  = (const float*)d_in[5];
    float*       out   = (float*)d_out;

    const int* src = ei;
    const int* dst = ei + N_EDGES;

    k_zero<<<(N_NODES + 255) / 256, 256>>>();
    k_count<<<(N_EDGES + 255) / 256, 256>>>(src, dst);
    k_layernorm<<<(N_NODES * 32 + 255) / 256, 256>>>(h, gamma, beta);
    k_scan_local<<<SCAN_BLOCKS, 1024>>>();
    k_scan_block<<<1, 64>>>();
    k_fill_csr<<<(N_EDGES + 255) / 256, 256>>>(src, dst);
    k_aggregate<<<(N_NODES * 32 + 255) / 256, 256>>>();
    k_gemm<<<(N_NODES + GBM - 1) / GBM, 256>>>(W, bias, out);
}

// round 5
// speedup vs baseline: 2.4756x; 1.2845x over previous
#include <cuda_runtime.h>
#include <cuda_fp16.h>
#include <stdint.h>

#define N_NODES 50000
#define N_EDGES 600000
#define D 128
#define EPS 1e-5f
#define SCAN_BLOCKS 49   // ceil(50000/1024)

// ---------------- scratch (device globals; no allocations allowed) ----------
__device__ __half g_hn_h[N_NODES * D];   // layernormed features (fp16)
__device__ __half g_msg_h[N_NODES * D];  // aggregated message (fp16)
__device__ int    g_deg_in[N_NODES];
__device__ int    g_deg_out[N_NODES];
__device__ float  g_inv_in[N_NODES];
__device__ float  g_inv_out[N_NODES];
__device__ int    g_rowstart[N_NODES];   // block-local exclusive scan of deg_in
__device__ int    g_blocksum[SCAN_BLOCKS];
__device__ int    g_blockoff[SCAN_BLOCKS];
__device__ int    g_cursor[N_NODES];
__device__ int    g_csr_src[N_EDGES];

__device__ __forceinline__ int row_begin(int w) {
    return g_rowstart[w] + g_blockoff[w >> 10];
}

// ---------------- K0: zero counters -----------------------------------------
__global__ void k_zero() {
    int i = blockIdx.x * blockDim.x + threadIdx.x;
    if (i < N_NODES) {
        g_deg_in[i] = 0;
        g_deg_out[i] = 0;
        g_cursor[i] = 0;
    }
}

// ---------------- K1: degree counts -----------------------------------------
__global__ void k_count(const int* __restrict__ src,
                        const int* __restrict__ dst) {
    int i = blockIdx.x * blockDim.x + threadIdx.x;
    if (i < N_EDGES) {
        atomicAdd(&g_deg_out[src[i]], 1);
        atomicAdd(&g_deg_in[dst[i]], 1);
    }
}

// ---------------- K2: LayerNorm (warp per row) -> fp16, + inv-sqrt degrees --
__global__ void k_layernorm(const float* __restrict__ h,
                            const float* __restrict__ gamma,
                            const float* __restrict__ beta) {
    int warp = (blockIdx.x * blockDim.x + threadIdx.x) >> 5;
    int lane = threadIdx.x & 31;
    if (warp >= N_NODES) return;

    float4 v = ((const float4*)h)[warp * 32 + lane];
    float s  = v.x + v.y + v.z + v.w;
    float sq = v.x * v.x + v.y * v.y + v.z * v.z + v.w * v.w;
    #pragma unroll
    for (int off = 16; off > 0; off >>= 1) {
        s  += __shfl_xor_sync(0xFFFFFFFF, s,  off);
        sq += __shfl_xor_sync(0xFFFFFFFF, sq, off);
    }
    float mu  = s * (1.0f / D);
    float var = sq * (1.0f / D) - mu * mu;
    float rs  = rsqrtf(var + EPS);

    float4 g = ((const float4*)gamma)[lane];
    float4 b = ((const float4*)beta)[lane];
    float ox = (v.x - mu) * rs * g.x + b.x;
    float oy = (v.y - mu) * rs * g.y + b.y;
    float oz = (v.z - mu) * rs * g.z + b.z;
    float ow = (v.w - mu) * rs * g.w + b.w;

    __half2 h0 = __float22half2_rn(make_float2(ox, oy));
    __half2 h1 = __float22half2_rn(make_float2(oz, ow));
    uint2 pack;
    pack.x = *(uint32_t*)&h0;
    pack.y = *(uint32_t*)&h1;
    ((uint2*)g_hn_h)[warp * 32 + lane] = pack;

    if (lane == 0) {
        int din  = g_deg_in[warp];
        int dout = g_deg_out[warp];
        g_inv_in[warp]  = rsqrtf((float)(din  < 1 ? 1 : din));
        g_inv_out[warp] = rsqrtf((float)(dout < 1 ? 1 : dout));
    }
}

// ---------------- K3a: per-block exclusive scan of deg_in -------------------
__global__ __launch_bounds__(1024)
void k_scan_local() {
    __shared__ int warp_sums[32];
    int t = threadIdx.x;
    int i = blockIdx.x * 1024 + t;
    int lane = t & 31;
    int wid = t >> 5;

    int v = (i < N_NODES) ? g_deg_in[i] : 0;
    int incl = v;
    #pragma unroll
    for (int off = 1; off < 32; off <<= 1) {
        int n = __shfl_up_sync(0xFFFFFFFF, incl, off);
        if (lane >= off) incl += n;
    }
    if (lane == 31) warp_sums[wid] = incl;
    __syncthreads();
    if (wid == 0) {
        int ws = warp_sums[lane];
        int wi = ws;
        #pragma unroll
        for (int off = 1; off < 32; off <<= 1) {
            int n = __shfl_up_sync(0xFFFFFFFF, wi, off);
            if (lane >= off) wi += n;
        }
        warp_sums[lane] = wi - ws;   // exclusive warp offset
        if (lane == 31) g_blocksum[blockIdx.x] = wi;
    }
    __syncthreads();
    if (i < N_NODES)
        g_rowstart[i] = incl - v + warp_sums[wid];
}

// ---------------- K3b: scan the 49 block sums -> blockoff -------------------
__global__ void k_scan_block() {
    __shared__ int sh[64];
    int t = threadIdx.x;
    int v = (t < SCAN_BLOCKS) ? g_blocksum[t] : 0;
    sh[t] = v;
    __syncthreads();
    #pragma unroll
    for (int off = 1; off < 64; off <<= 1) {
        int x = (t >= off) ? sh[t - off] : 0;
        __syncthreads();
        sh[t] += x;
        __syncthreads();
    }
    if (t < SCAN_BLOCKS)
        g_blockoff[t] = sh[t] - v;   // exclusive
}

// ---------------- K4: scatter edges into CSR-by-destination ------------------
__global__ void k_fill_csr(const int* __restrict__ src,
                           const int* __restrict__ dst) {
    int i = blockIdx.x * blockDim.x + threadIdx.x;
    if (i < N_EDGES) {
        int d = dst[i];
        int pos = atomicAdd(&g_cursor[d], 1);
        g_csr_src[row_begin(d) + pos] = src[i];
    }
}

// ---------------- K5: aggregation (warp per destination node, fp16 gather) ---
__global__ void k_aggregate() {
    int warp = (blockIdx.x * blockDim.x + threadIdx.x) >> 5;
    int lane = threadIdx.x & 31;
    if (warp >= N_NODES) return;

    int e0 = row_begin(warp);
    int e1 = (warp + 1 < N_NODES) ? row_begin(warp + 1) : N_EDGES;

    float ax = 0.f, ay = 0.f, az = 0.f, aw = 0.f;
    for (int e = e0; e < e1; e++) {
        int s = g_csr_src[e];
        float w = g_inv_out[s];
        uint2 u = ((const uint2*)g_hn_h)[s * 32 + lane];   // 4 halfs
        float2 f0 = __half22float2(*(__half2*)&u.x);
        float2 f1 = __half22float2(*(__half2*)&u.y);
        ax += f0.x * w;
        ay += f0.y * w;
        az += f1.x * w;
        aw += f1.y * w;
    }
    float wi = g_inv_in[warp];
    __half2 h0 = __float22half2_rn(make_float2(ax * wi, ay * wi));
    __half2 h1 = __float22half2_rn(make_float2(az * wi, aw * wi));
    uint2 pack;
    pack.x = *(uint32_t*)&h0;
    pack.y = *(uint32_t*)&h1;
    ((uint2*)g_msg_h)[warp * 32 + lane] = pack;
}

// ---------------- K6: FP16 tensor-core GEMM  out = [hn|msg] @ W^T + b --------
// BM=128 rows, BN=128 (all cols), BK=64. 256 threads = 8 warps; warp w owns
// rows [w*16, w*16+16), computing 16 n-tiles via mma.m16n8k16 f16.
#define GBM 128
#define GBK 64
#define APAD 72   // halfs per A row (64 + 8 pad -> conflict-free)

__global__ __launch_bounds__(256, 2)
void k_gemm(const float* __restrict__ W,    // [128][256] row-major fp32
            const float* __restrict__ bias, // [128]
            float* __restrict__ out) {      // [N][128] fp32
    __shared__ __half As[GBM][APAD];        // A tile, row-major
    __shared__ __half Ws[128][APAD];        // W tile, n-major (k contiguous)

    int tid  = threadIdx.x;
    int warp = tid >> 5;
    int lane = tid & 31;
    int rowBase = blockIdx.x * GBM;

    float acc[16][4];
    #pragma unroll
    for (int j = 0; j < 16; j++)
        #pragma unroll
        for (int c = 0; c < 4; c++) acc[j][c] = 0.f;

    for (int kk = 0; kk < 2 * D; kk += GBK) {
        const __half* Asrc = (kk < D) ? g_hn_h : g_msg_h;
        int kOff = kk & (D - 1);

        // stage A tile: 128 rows x 64 halfs (1024 uint4 slots of 8 halfs)
        #pragma unroll
        for (int it = 0; it < 4; it++) {
            int id = tid + it * 256;
            int r  = id >> 3;          // 0..127
            int c8 = id & 7;           // 0..7 (8-half groups)
            int gr = rowBase + r;
            uint4 v = make_uint4(0u, 0u, 0u, 0u);
            if (gr < N_NODES)
                v = *(const uint4*)&Asrc[gr * D + kOff + c8 * 8];
            *(uint4*)&As[r][c8 * 8] = v;
        }
        // stage W tile: Ws[n][k] = (half)W[n][kk+k], 128 x 64 (2048 float4)
        #pragma unroll
        for (int it = 0; it < 8; it++) {
            int id = tid + it * 256;
            int n  = id >> 4;          // 0..127
            int c4 = id & 15;          // 0..15 (4-float groups)
            float4 v = *(const float4*)&W[n * 256 + kk + c4 * 4];
            __half2 h0 = __float22half2_rn(make_float2(v.x, v.y));
            __half2 h1 = __float22half2_rn(make_float2(v.z, v.w));
            uint2 p;
            p.x = *(uint32_t*)&h0;
            p.y = *(uint32_t*)&h1;
            *(uint2*)&Ws[n][c4 * 4] = p;
        }
        __syncthreads();

        int q = lane & 3;        // threadID_in_group
        int g = lane >> 2;       // groupID
        int r0 = warp * 16;
        #pragma unroll
        for (int k0 = 0; k0 < GBK; k0 += 16) {
            uint32_t a0 = *(const uint32_t*)&As[r0 + g][k0 + 2 * q];
            uint32_t a1 = *(const uint32_t*)&As[r0 + g + 8][k0 + 2 * q];
            uint32_t a2 = *(const uint32_t*)&As[r0 + g][k0 + 2 * q + 8];
            uint32_t a3 = *(const uint32_t*)&As[r0 + g + 8][k0 + 2 * q + 8];
            #pragma unroll
            for (int j = 0; j < 16; j++) {
                uint32_t b0 = *(const uint32_t*)&Ws[j * 8 + g][k0 + 2 * q];
                uint32_t b1 = *(const uint32_t*)&Ws[j * 8 + g][k0 + 2 * q + 8];
                asm volatile(
                    "mma.sync.aligned.m16n8k16.row.col.f32.f16.f16.f32 "
                    "{%0,%1,%2,%3}, {%4,%5,%6,%7}, {%8,%9}, {%0,%1,%2,%3};"
                    : "+f"(acc[j][0]), "+f"(acc[j][1]),
                      "+f"(acc[j][2]), "+f"(acc[j][3])
                    : "r"(a0), "r"(a1), "r"(a2), "r"(a3), "r"(b0), "r"(b1));
            }
        }
        __syncthreads();
    }

    // epilogue: bias + store (c0/c1 -> row g, cols 2q,2q+1; c2/c3 -> row g+8)
    int q = lane & 3;
    int g = lane >> 2;
    int row0 = rowBase + warp * 16 + g;
    int row1 = row0 + 8;
    #pragma unroll
    for (int j = 0; j < 16; j++) {
        int col = j * 8 + q * 2;
        float b0 = __ldg(&bias[col]);
        float b1 = __ldg(&bias[col + 1]);
        if (row0 < N_NODES) {
            float2 o = make_float2(acc[j][0] + b0, acc[j][1] + b1);
            *(float2*)&out[row0 * D + col] = o;
        }
        if (row1 < N_NODES) {
            float2 o = make_float2(acc[j][2] + b0, acc[j][3] + b1);
            *(float2*)&out[row1 * D + col] = o;
        }
    }
}

// ---------------- launcher ---------------------------------------------------
extern "C" void kernel_launch(void* const* d_in, const int* in_sizes, int n_in,
                              void* d_out, int out_size) {
    const float* h     = (const float*)d_in[0];
    const int*   ei    = (const int*)d_in[1];   // [2][E] int32
    const float* gamma = (const float*)d_in[2];
    const float* beta  = (const float*)d_in[3];
    const float* W     = (const float*)d_in[4];
    const float* bias  = (const float*)d_in[5];
    float*       out   = (float*)d_out;

    const int* src = ei;
    const int* dst = ei + N_EDGES;

    k_zero<<<(N_NODES + 255) / 256, 256>>>();
    k_count<<<(N_EDGES + 255) / 256, 256>>>(src, dst);
    k_layernorm<<<(N_NODES * 32 + 255) / 256, 256>>>(h, gamma, beta);
    k_scan_local<<<SCAN_BLOCKS, 1024>>>();
    k_scan_block<<<1, 64>>>();
    k_fill_csr<<<(N_EDGES + 255) / 256, 256>>>(src, dst);
    k_aggregate<<<(N_NODES * 32 + 255) / 256, 256>>>();
    k_gemm<<<(N_NODES + GBM - 1) / GBM, 256>>>(W, bias, out);
}

// round 8
// speedup vs baseline: 2.7256x; 1.1010x over previous
#include <cuda_runtime.h>
#include <cuda_fp16.h>
#include <stdint.h>

#define N_NODES 50000
#define N_EDGES 600000
#define D 128
#define EPS 1e-5f
#define SCAN_BLOCKS 49   // ceil(50000/1024)

// ---------------- scratch (device globals; no allocations allowed) ----------
__device__ __half g_hn_h[N_NODES * D];   // layernormed features (fp16)
__device__ __half g_msg_h[N_NODES * D];  // aggregated message (fp16)
__device__ __half g_W_h[D * 2 * D];      // W converted to fp16 (row-major [128][256])
__device__ int    g_counters[3 * N_NODES];  // [deg_in | deg_out | cursor], one memset
__device__ float  g_inv_in[N_NODES];
__device__ float  g_inv_out[N_NODES];
__device__ int    g_rowstart[N_NODES];   // block-local exclusive scan of deg_in
__device__ int    g_blocksum[SCAN_BLOCKS];
__device__ int    g_blockoff[SCAN_BLOCKS];
__device__ int    g_csr_src[N_EDGES];

#define DEG_IN  (g_counters)
#define DEG_OUT (g_counters + N_NODES)
#define CURSOR  (g_counters + 2 * N_NODES)

__device__ __forceinline__ int row_begin(int w) {
    return g_rowstart[w] + g_blockoff[w >> 10];
}

// ---------------- K1: degree counts -----------------------------------------
__global__ void k_count(const int* __restrict__ src,
                        const int* __restrict__ dst) {
    int i = blockIdx.x * blockDim.x + threadIdx.x;
    if (i < N_EDGES) {
        atomicAdd(&DEG_OUT[__ldg(&src[i])], 1);
        atomicAdd(&DEG_IN[__ldg(&dst[i])], 1);
    }
}

// ---------------- K1b: convert W to fp16 -------------------------------------
__global__ void k_convw(const float* __restrict__ W) {
    int i = blockIdx.x * blockDim.x + threadIdx.x;   // over float4 groups
    if (i < (D * 2 * D) / 4) {
        float4 v = *(const float4*)&W[i * 4];
        __half2 h0 = __float22half2_rn(make_float2(v.x, v.y));
        __half2 h1 = __float22half2_rn(make_float2(v.z, v.w));
        uint2 p;
        p.x = *(uint32_t*)&h0;
        p.y = *(uint32_t*)&h1;
        *(uint2*)&g_W_h[i * 4] = p;
    }
}

// ---------------- K2: LayerNorm (warp per row) -> fp16, + inv-sqrt degrees --
__global__ void k_layernorm(const float* __restrict__ h,
                            const float* __restrict__ gamma,
                            const float* __restrict__ beta) {
    int warp = (blockIdx.x * blockDim.x + threadIdx.x) >> 5;
    int lane = threadIdx.x & 31;
    if (warp >= N_NODES) return;

    float4 v = ((const float4*)h)[warp * 32 + lane];
    float s  = v.x + v.y + v.z + v.w;
    float sq = v.x * v.x + v.y * v.y + v.z * v.z + v.w * v.w;
    #pragma unroll
    for (int off = 16; off > 0; off >>= 1) {
        s  += __shfl_xor_sync(0xFFFFFFFF, s,  off);
        sq += __shfl_xor_sync(0xFFFFFFFF, sq, off);
    }
    float mu  = s * (1.0f / D);
    float var = sq * (1.0f / D) - mu * mu;
    float rs  = rsqrtf(var + EPS);

    float4 g = ((const float4*)gamma)[lane];
    float4 b = ((const float4*)beta)[lane];
    float ox = (v.x - mu) * rs * g.x + b.x;
    float oy = (v.y - mu) * rs * g.y + b.y;
    float oz = (v.z - mu) * rs * g.z + b.z;
    float ow = (v.w - mu) * rs * g.w + b.w;

    __half2 h0 = __float22half2_rn(make_float2(ox, oy));
    __half2 h1 = __float22half2_rn(make_float2(oz, ow));
    uint2 pack;
    pack.x = *(uint32_t*)&h0;
    pack.y = *(uint32_t*)&h1;
    ((uint2*)g_hn_h)[warp * 32 + lane] = pack;

    if (lane == 0) {
        int din  = DEG_IN[warp];
        int dout = DEG_OUT[warp];
        g_inv_in[warp]  = rsqrtf((float)(din  < 1 ? 1 : din));
        g_inv_out[warp] = rsqrtf((float)(dout < 1 ? 1 : dout));
    }
}

// ---------------- K3a: per-block exclusive scan of deg_in -------------------
__global__ __launch_bounds__(1024)
void k_scan_local() {
    __shared__ int warp_sums[32];
    int t = threadIdx.x;
    int i = blockIdx.x * 1024 + t;
    int lane = t & 31;
    int wid = t >> 5;

    int v = (i < N_NODES) ? DEG_IN[i] : 0;
    int incl = v;
    #pragma unroll
    for (int off = 1; off < 32; off <<= 1) {
        int n = __shfl_up_sync(0xFFFFFFFF, incl, off);
        if (lane >= off) incl += n;
    }
    if (lane == 31) warp_sums[wid] = incl;
    __syncthreads();
    if (wid == 0) {
        int ws = warp_sums[lane];
        int wi = ws;
        #pragma unroll
        for (int off = 1; off < 32; off <<= 1) {
            int n = __shfl_up_sync(0xFFFFFFFF, wi, off);
            if (lane >= off) wi += n;
        }
        warp_sums[lane] = wi - ws;   // exclusive warp offset
        if (lane == 31) g_blocksum[blockIdx.x] = wi;
    }
    __syncthreads();
    if (i < N_NODES)
        g_rowstart[i] = incl - v + warp_sums[wid];
}

// ---------------- K3b: scan the 49 block sums -> blockoff -------------------
__global__ void k_scan_block() {
    __shared__ int sh[64];
    int t = threadIdx.x;
    int v = (t < SCAN_BLOCKS) ? g_blocksum[t] : 0;
    sh[t] = v;
    __syncthreads();
    #pragma unroll
    for (int off = 1; off < 64; off <<= 1) {
        int x = (t >= off) ? sh[t - off] : 0;
        __syncthreads();
        sh[t] += x;
        __syncthreads();
    }
    if (t < SCAN_BLOCKS)
        g_blockoff[t] = sh[t] - v;   // exclusive
}

// ---------------- K4: scatter edges into CSR-by-destination ------------------
__global__ void k_fill_csr(const int* __restrict__ src,
                           const int* __restrict__ dst) {
    int i = blockIdx.x * blockDim.x + threadIdx.x;
    if (i < N_EDGES) {
        int d = __ldg(&dst[i]);
        int pos = atomicAdd(&CURSOR[d], 1);
        g_csr_src[row_begin(d) + pos] = __ldg(&src[i]);
    }
}

// ---------------- K5: aggregation (warp per dst node, fp16, unroll 2) --------
__global__ void k_aggregate() {
    int warp = (blockIdx.x * blockDim.x + threadIdx.x) >> 5;
    int lane = threadIdx.x & 31;
    if (warp >= N_NODES) return;

    int e0 = row_begin(warp);
    int e1 = (warp + 1 < N_NODES) ? row_begin(warp + 1) : N_EDGES;

    float ax0 = 0.f, ay0 = 0.f, az0 = 0.f, aw0 = 0.f;
    float ax1 = 0.f, ay1 = 0.f, az1 = 0.f, aw1 = 0.f;
    int e = e0;
    for (; e + 2 <= e1; e += 2) {
        int s0 = __ldg(&g_csr_src[e]);
        int s1 = __ldg(&g_csr_src[e + 1]);
        float w0 = g_inv_out[s0];
        float w1 = g_inv_out[s1];
        uint2 u0 = ((const uint2*)g_hn_h)[s0 * 32 + lane];
        uint2 u1 = ((const uint2*)g_hn_h)[s1 * 32 + lane];
        float2 f00 = __half22float2(*(__half2*)&u0.x);
        float2 f01 = __half22float2(*(__half2*)&u0.y);
        float2 f10 = __half22float2(*(__half2*)&u1.x);
        float2 f11 = __half22float2(*(__half2*)&u1.y);
        ax0 += f00.x * w0;  ay0 += f00.y * w0;
        az0 += f01.x * w0;  aw0 += f01.y * w0;
        ax1 += f10.x * w1;  ay1 += f10.y * w1;
        az1 += f11.x * w1;  aw1 += f11.y * w1;
    }
    if (e < e1) {
        int s = __ldg(&g_csr_src[e]);
        float w = g_inv_out[s];
        uint2 u = ((const uint2*)g_hn_h)[s * 32 + lane];
        float2 f0 = __half22float2(*(__half2*)&u.x);
        float2 f1 = __half22float2(*(__half2*)&u.y);
        ax0 += f0.x * w;  ay0 += f0.y * w;
        az0 += f1.x * w;  aw0 += f1.y * w;
    }
    float wi = g_inv_in[warp];
    __half2 h0 = __float22half2_rn(make_float2((ax0 + ax1) * wi, (ay0 + ay1) * wi));
    __half2 h1 = __float22half2_rn(make_float2((az0 + az1) * wi, (aw0 + aw1) * wi));
    uint2 pack;
    pack.x = *(uint32_t*)&h0;
    pack.y = *(uint32_t*)&h1;
    ((uint2*)g_msg_h)[warp * 32 + lane] = pack;
}

// ---------------- K6: FP16 tensor-core GEMM  out = [hn|msg] @ W^T + b --------
#define GBM 128
#define GBK 64
#define APAD 72   // halfs per row (64 + 8 pad -> conflict-free)

__global__ __launch_bounds__(256, 2)
void k_gemm(const float* __restrict__ bias, // [128]
            float* __restrict__ out) {      // [N][128] fp32
    __shared__ __half As[GBM][APAD];        // A tile, row-major
    __shared__ __half Ws[128][APAD];        // W tile, n-major (k contiguous)

    int tid  = threadIdx.x;
    int warp = tid >> 5;
    int lane = tid & 31;
    int rowBase = blockIdx.x * GBM;

    float acc[16][4];
    #pragma unroll
    for (int j = 0; j < 16; j++)
        #pragma unroll
        for (int c = 0; c < 4; c++) acc[j][c] = 0.f;

    for (int kk = 0; kk < 2 * D; kk += GBK) {
        const __half* Asrc = (kk < D) ? g_hn_h : g_msg_h;
        int kOff = kk & (D - 1);

        // stage A tile: 128 rows x 64 halfs (1024 uint4 slots of 8 halfs)
        #pragma unroll
        for (int it = 0; it < 4; it++) {
            int id = tid + it * 256;
            int r  = id >> 3;          // 0..127
            int c8 = id & 7;           // 0..7
            int gr = rowBase + r;
            uint4 v = make_uint4(0u, 0u, 0u, 0u);
            if (gr < N_NODES)
                v = *(const uint4*)&Asrc[gr * D + kOff + c8 * 8];
            *(uint4*)&As[r][c8 * 8] = v;
        }
        // stage W tile from pre-converted fp16: Ws[n][k] = g_W_h[n*256 + kk + k]
        #pragma unroll
        for (int it = 0; it < 4; it++) {
            int id = tid + it * 256;
            int n  = id >> 3;          // 0..127
            int c8 = id & 7;           // 0..7
            uint4 v = *(const uint4*)&g_W_h[n * 256 + kk + c8 * 8];
            *(uint4*)&Ws[n][c8 * 8] = v;
        }
        __syncthreads();

        int q = lane & 3;        // threadID_in_group
        int g = lane >> 2;       // groupID
        int r0 = warp * 16;
        #pragma unroll
        for (int k0 = 0; k0 < GBK; k0 += 16) {
            uint32_t a0 = *(const uint32_t*)&As[r0 + g][k0 + 2 * q];
            uint32_t a1 = *(const uint32_t*)&As[r0 + g + 8][k0 + 2 * q];
            uint32_t a2 = *(const uint32_t*)&As[r0 + g][k0 + 2 * q + 8];
            uint32_t a3 = *(const uint32_t*)&As[r0 + g + 8][k0 + 2 * q + 8];
            #pragma unroll
            for (int j = 0; j < 16; j++) {
                uint32_t b0 = *(const uint32_t*)&Ws[j * 8 + g][k0 + 2 * q];
                uint32_t b1 = *(const uint32_t*)&Ws[j * 8 + g][k0 + 2 * q + 8];
                asm volatile(
                    "mma.sync.aligned.m16n8k16.row.col.f32.f16.f16.f32 "
                    "{%0,%1,%2,%3}, {%4,%5,%6,%7}, {%8,%9}, {%0,%1,%2,%3};"
                    : "+f"(acc[j][0]), "+f"(acc[j][1]),
                      "+f"(acc[j][2]), "+f"(acc[j][3])
                    : "r"(a0), "r"(a1), "r"(a2), "r"(a3), "r"(b0), "r"(b1));
            }
        }
        __syncthreads();
    }

    // epilogue: bias + store
    int q = lane & 3;
    int g = lane >> 2;
    int row0 = rowBase + warp * 16 + g;
    int row1 = row0 + 8;
    #pragma unroll
    for (int j = 0; j < 16; j++) {
        int col = j * 8 + q * 2;
        float b0 = __ldg(&bias[col]);
        float b1 = __ldg(&bias[col + 1]);
        if (row0 < N_NODES) {
            float2 o = make_float2(acc[j][0] + b0, acc[j][1] + b1);
            *(float2*)&out[row0 * D + col] = o;
        }
        if (row1 < N_NODES) {
            float2 o = make_float2(acc[j][2] + b0, acc[j][3] + b1);
            *(float2*)&out[row1 * D + col] = o;
        }
    }
}

// ---------------- launcher ---------------------------------------------------
extern "C" void kernel_launch(void* const* d_in, const int* in_sizes, int n_in,
                              void* d_out, int out_size) {
    const float* h     = (const float*)d_in[0];
    const int*   ei    = (const int*)d_in[1];   // [2][E] int32
    const float* gamma = (const float*)d_in[2];
    const float* beta  = (const float*)d_in[3];
    const float* W     = (const float*)d_in[4];
    const float* bias  = (const float*)d_in[5];
    float*       out   = (float*)d_out;

    const int* src = ei;
    const int* dst = ei + N_EDGES;

    void* counters_ptr = nullptr;
    cudaGetSymbolAddress(&counters_ptr, g_counters);
    cudaMemsetAsync(counters_ptr, 0, 3 * N_NODES * sizeof(int), 0);

    k_count<<<(N_EDGES + 255) / 256, 256>>>(src, dst);
    k_convw<<<((D * 2 * D / 4) + 255) / 256, 256>>>(W);
    k_layernorm<<<(N_NODES * 32 + 255) / 256, 256>>>(h, gamma, beta);
    k_scan_local<<<SCAN_BLOCKS, 1024>>>();
    k_scan_block<<<1, 64>>>();
    k_fill_csr<<<(N_EDGES + 255) / 256, 256>>>(src, dst);
    k_aggregate<<<(N_NODES * 32 + 255) / 256, 256>>>();
    k_gemm<<<(N_NODES + GBM - 1) / GBM, 256>>>(bias, out);
}

// round 9
// speedup vs baseline: 2.8654x; 1.0513x over previous
#include <cuda_runtime.h>
#include <cuda_fp16.h>
#include <stdint.h>

#define N_NODES 50000
#define N_EDGES 600000
#define D 128
#define EPS 1e-5f
#define SCAN_BLOCKS 49   // ceil(50000/1024)

// ---------------- scratch (device globals; no allocations allowed) ----------
__device__ __half g_hn_h[N_NODES * D];   // layernormed features (fp16)
__device__ __half g_msg_h[N_NODES * D];  // aggregated message (fp16)
__device__ __half g_W_h[D * 2 * D];      // W fp16 (row-major [128][256])
__device__ int    g_counters[2 * N_NODES];  // [deg_in | deg_out], one memset
__device__ float  g_inv_in[N_NODES];
__device__ float  g_inv_out[N_NODES];
__device__ int    g_rowstart[N_NODES];   // block-local exclusive scan of deg_in
__device__ int    g_blocksum[SCAN_BLOCKS];
__device__ int    g_blockoff[SCAN_BLOCKS];
__device__ int    g_epos[N_EDGES];       // per-edge rank within destination
__device__ int    g_csr_src[N_EDGES];

#define DEG_IN  (g_counters)
#define DEG_OUT (g_counters + N_NODES)

__device__ __forceinline__ int row_begin(int w) {
    return g_rowstart[w] + g_blockoff[w >> 10];
}

__device__ __forceinline__ void cp_async16(void* smem, const void* gmem) {
    uint32_t s = (uint32_t)__cvta_generic_to_shared(smem);
    asm volatile("cp.async.cg.shared.global [%0], [%1], 16;" :: "r"(s), "l"(gmem));
}
#define CP_COMMIT() asm volatile("cp.async.commit_group;")
#define CP_WAIT(n)  asm volatile("cp.async.wait_group %0;" :: "n"(n))

// ---------------- K1: degree counts + per-edge rank --------------------------
__global__ void k_count(const int* __restrict__ src,
                        const int* __restrict__ dst) {
    int i = blockIdx.x * blockDim.x + threadIdx.x;
    if (i < N_EDGES) {
        atomicAdd(&DEG_OUT[__ldg(&src[i])], 1);
        g_epos[i] = atomicAdd(&DEG_IN[__ldg(&dst[i])], 1);
    }
}

// ---------------- K1b: convert W to fp16 -------------------------------------
__global__ void k_convw(const float* __restrict__ W) {
    int i = blockIdx.x * blockDim.x + threadIdx.x;   // over float4 groups
    if (i < (D * 2 * D) / 4) {
        float4 v = *(const float4*)&W[i * 4];
        __half2 h0 = __float22half2_rn(make_float2(v.x, v.y));
        __half2 h1 = __float22half2_rn(make_float2(v.z, v.w));
        uint2 p;
        p.x = *(uint32_t*)&h0;
        p.y = *(uint32_t*)&h1;
        *(uint2*)&g_W_h[i * 4] = p;
    }
}

// ---------------- K2: LayerNorm (warp per row) -> fp16 (pure) ----------------
__global__ void k_layernorm(const float* __restrict__ h,
                            const float* __restrict__ gamma,
                            const float* __restrict__ beta) {
    int warp = (blockIdx.x * blockDim.x + threadIdx.x) >> 5;
    int lane = threadIdx.x & 31;
    if (warp >= N_NODES) return;

    float4 v = ((const float4*)h)[warp * 32 + lane];
    float s  = v.x + v.y + v.z + v.w;
    float sq = v.x * v.x + v.y * v.y + v.z * v.z + v.w * v.w;
    #pragma unroll
    for (int off = 16; off > 0; off >>= 1) {
        s  += __shfl_xor_sync(0xFFFFFFFF, s,  off);
        sq += __shfl_xor_sync(0xFFFFFFFF, sq, off);
    }
    float mu  = s * (1.0f / D);
    float var = sq * (1.0f / D) - mu * mu;
    float rs  = rsqrtf(var + EPS);

    float4 g = ((const float4*)gamma)[lane];
    float4 b = ((const float4*)beta)[lane];
    float ox = (v.x - mu) * rs * g.x + b.x;
    float oy = (v.y - mu) * rs * g.y + b.y;
    float oz = (v.z - mu) * rs * g.z + b.z;
    float ow = (v.w - mu) * rs * g.w + b.w;

    __half2 h0 = __float22half2_rn(make_float2(ox, oy));
    __half2 h1 = __float22half2_rn(make_float2(oz, ow));
    uint2 pack;
    pack.x = *(uint32_t*)&h0;
    pack.y = *(uint32_t*)&h1;
    ((uint2*)g_hn_h)[warp * 32 + lane] = pack;
}

// ---------------- K3a: block scan of deg_in + inv-sqrt degrees ---------------
__global__ __launch_bounds__(1024)
void k_scan_local() {
    __shared__ int warp_sums[32];
    int t = threadIdx.x;
    int i = blockIdx.x * 1024 + t;
    int lane = t & 31;
    int wid = t >> 5;

    int v = 0;
    if (i < N_NODES) {
        v = DEG_IN[i];
        int dout = DEG_OUT[i];
        g_inv_in[i]  = rsqrtf((float)(v    < 1 ? 1 : v));
        g_inv_out[i] = rsqrtf((float)(dout < 1 ? 1 : dout));
    }
    int incl = v;
    #pragma unroll
    for (int off = 1; off < 32; off <<= 1) {
        int n = __shfl_up_sync(0xFFFFFFFF, incl, off);
        if (lane >= off) incl += n;
    }
    if (lane == 31) warp_sums[wid] = incl;
    __syncthreads();
    if (wid == 0) {
        int ws = warp_sums[lane];
        int wi = ws;
        #pragma unroll
        for (int off = 1; off < 32; off <<= 1) {
            int n = __shfl_up_sync(0xFFFFFFFF, wi, off);
            if (lane >= off) wi += n;
        }
        warp_sums[lane] = wi - ws;   // exclusive warp offset
        if (lane == 31) g_blocksum[blockIdx.x] = wi;
    }
    __syncthreads();
    if (i < N_NODES)
        g_rowstart[i] = incl - v + warp_sums[wid];
}

// ---------------- K3b: scan the 49 block sums -> blockoff -------------------
__global__ void k_scan_block() {
    __shared__ int sh[64];
    int t = threadIdx.x;
    int v = (t < SCAN_BLOCKS) ? g_blocksum[t] : 0;
    sh[t] = v;
    __syncthreads();
    #pragma unroll
    for (int off = 1; off < 64; off <<= 1) {
        int x = (t >= off) ? sh[t - off] : 0;
        __syncthreads();
        sh[t] += x;
        __syncthreads();
    }
    if (t < SCAN_BLOCKS)
        g_blockoff[t] = sh[t] - v;   // exclusive
}

// ---------------- K4: scatter edges into CSR (no atomics) --------------------
__global__ void k_fill_csr(const int* __restrict__ src,
                           const int* __restrict__ dst) {
    int i = blockIdx.x * blockDim.x + threadIdx.x;
    if (i < N_EDGES) {
        int d = __ldg(&dst[i]);
        g_csr_src[row_begin(d) + g_epos[i]] = __ldg(&src[i]);
    }
}

// ---------------- K5: aggregation (warp per dst node, fp16, unroll 2) --------
__global__ void k_aggregate() {
    int warp = (blockIdx.x * blockDim.x + threadIdx.x) >> 5;
    int lane = threadIdx.x & 31;
    if (warp >= N_NODES) return;

    int e0 = row_begin(warp);
    int e1 = (warp + 1 < N_NODES) ? row_begin(warp + 1) : N_EDGES;

    float ax0 = 0.f, ay0 = 0.f, az0 = 0.f, aw0 = 0.f;
    float ax1 = 0.f, ay1 = 0.f, az1 = 0.f, aw1 = 0.f;
    int e = e0;
    for (; e + 2 <= e1; e += 2) {
        int s0 = __ldg(&g_csr_src[e]);
        int s1 = __ldg(&g_csr_src[e + 1]);
        float w0 = g_inv_out[s0];
        float w1 = g_inv_out[s1];
        uint2 u0 = ((const uint2*)g_hn_h)[s0 * 32 + lane];
        uint2 u1 = ((const uint2*)g_hn_h)[s1 * 32 + lane];
        float2 f00 = __half22float2(*(__half2*)&u0.x);
        float2 f01 = __half22float2(*(__half2*)&u0.y);
        float2 f10 = __half22float2(*(__half2*)&u1.x);
        float2 f11 = __half22float2(*(__half2*)&u1.y);
        ax0 += f00.x * w0;  ay0 += f00.y * w0;
        az0 += f01.x * w0;  aw0 += f01.y * w0;
        ax1 += f10.x * w1;  ay1 += f10.y * w1;
        az1 += f11.x * w1;  aw1 += f11.y * w1;
    }
    if (e < e1) {
        int s = __ldg(&g_csr_src[e]);
        float w = g_inv_out[s];
        uint2 u = ((const uint2*)g_hn_h)[s * 32 + lane];
        float2 f0 = __half22float2(*(__half2*)&u.x);
        float2 f1 = __half22float2(*(__half2*)&u.y);
        ax0 += f0.x * w;  ay0 += f0.y * w;
        az0 += f1.x * w;  aw0 += f1.y * w;
    }
    float wi = g_inv_in[warp];
    __half2 h0 = __float22half2_rn(make_float2((ax0 + ax1) * wi, (ay0 + ay1) * wi));
    __half2 h1 = __float22half2_rn(make_float2((az0 + az1) * wi, (aw0 + aw1) * wi));
    uint2 pack;
    pack.x = *(uint32_t*)&h0;
    pack.y = *(uint32_t*)&h1;
    ((uint2*)g_msg_h)[warp * 32 + lane] = pack;
}

// ---------------- K6: FP16 MMA GEMM, cp.async pipelined ----------------------
// A tiles (128x64 halfs) double-buffered; W (128x256 halfs) resident in smem.
#define GBM 128
#define APAD 72    // A row stride in halfs
#define WPAD 264   // W row stride in halfs
#define SMEM_GEMM ((2 * GBM * APAD + 128 * WPAD) * 2)   // 104448 bytes

__global__ __launch_bounds__(256, 2)
void k_gemm(const float* __restrict__ bias, // [128]
            float* __restrict__ out) {      // [N][128] fp32
    extern __shared__ __half sm[];
    __half* As = sm;                        // [2][128][APAD]
    __half* Ws = sm + 2 * GBM * APAD;       // [128][WPAD]

    int tid  = threadIdx.x;
    int warp = tid >> 5;
    int lane = tid & 31;
    int rowBase = blockIdx.x * GBM;

    // issue A-tile loads for k-iteration i into buffer i&1
    auto issue_a = [&](int i) {
        const __half* Asrc = (i < 2) ? g_hn_h : g_msg_h;
        int kOff = (i * 64) & (D - 1);
        int buf = i & 1;
        #pragma unroll
        for (int it = 0; it < 4; it++) {
            int id = tid + it * 256;
            int r  = id >> 3;
            int c8 = id & 7;
            int gr = rowBase + r;
            if (gr > N_NODES - 1) gr = N_NODES - 1;   // clamp; result discarded
            cp_async16(&As[(buf * GBM + r) * APAD + c8 * 8],
                       &Asrc[gr * D + kOff + c8 * 8]);
        }
    };

    // prologue: whole W + first A tile in one group
    #pragma unroll
    for (int it = 0; it < 16; it++) {
        int id = tid + it * 256;    // 0..4095
        int n  = id >> 5;
        int c8 = id & 31;
        cp_async16(&Ws[n * WPAD + c8 * 8], &g_W_h[n * 256 + c8 * 8]);
    }
    issue_a(0);
    CP_COMMIT();

    float acc[16][4];
    #pragma unroll
    for (int j = 0; j < 16; j++)
        #pragma unroll
        for (int c = 0; c < 4; c++) acc[j][c] = 0.f;

    int q = lane & 3;
    int g = lane >> 2;
    int r0 = warp * 16;

    #pragma unroll
    for (int i = 0; i < 4; i++) {
        if (i < 3) {
            issue_a(i + 1);
            CP_COMMIT();
            CP_WAIT(1);
        } else {
            CP_WAIT(0);
        }
        __syncthreads();

        const __half* Ab = &As[(i & 1) * GBM * APAD];
        int kw = i * 64;   // k offset into Ws rows
        #pragma unroll
        for (int k0 = 0; k0 < 64; k0 += 16) {
            uint32_t a0 = *(const uint32_t*)&Ab[(r0 + g) * APAD + k0 + 2 * q];
            uint32_t a1 = *(const uint32_t*)&Ab[(r0 + g + 8) * APAD + k0 + 2 * q];
            uint32_t a2 = *(const uint32_t*)&Ab[(r0 + g) * APAD + k0 + 2 * q + 8];
            uint32_t a3 = *(const uint32_t*)&Ab[(r0 + g + 8) * APAD + k0 + 2 * q + 8];
            #pragma unroll
            for (int j = 0; j < 16; j++) {
                uint32_t b0 = *(const uint32_t*)&Ws[(j * 8 + g) * WPAD + kw + k0 + 2 * q];
                uint32_t b1 = *(const uint32_t*)&Ws[(j * 8 + g) * WPAD + kw + k0 + 2 * q + 8];
                asm volatile(
                    "mma.sync.aligned.m16n8k16.row.col.f32.f16.f16.f32 "
                    "{%0,%1,%2,%3}, {%4,%5,%6,%7}, {%8,%9}, {%0,%1,%2,%3};"
                    : "+f"(acc[j][0]), "+f"(acc[j][1]),
                      "+f"(acc[j][2]), "+f"(acc[j][3])
                    : "r"(a0), "r"(a1), "r"(a2), "r"(a3), "r"(b0), "r"(b1));
            }
        }
        __syncthreads();
    }

    // epilogue: bias + store
    int row0 = rowBase + warp * 16 + g;
    int row1 = row0 + 8;
    #pragma unroll
    for (int j = 0; j < 16; j++) {
        int col = j * 8 + q * 2;
        float b0 = __ldg(&bias[col]);
        float b1 = __ldg(&bias[col + 1]);
        if (row0 < N_NODES) {
            float2 o = make_float2(acc[j][0] + b0, acc[j][1] + b1);
            *(float2*)&out[row0 * D + col] = o;
        }
        if (row1 < N_NODES) {
            float2 o = make_float2(acc[j][2] + b0, acc[j][3] + b1);
            *(float2*)&out[row1 * D + col] = o;
        }
    }
}

// ---------------- launcher (fork-join streams inside the capture) -----------
extern "C" void kernel_launch(void* const* d_in, const int* in_sizes, int n_in,
                              void* d_out, int out_size) {
    const float* h     = (const float*)d_in[0];
    const int*   ei    = (const int*)d_in[1];   // [2][E] int32
    const float* gamma = (const float*)d_in[2];
    const float* beta  = (const float*)d_in[3];
    const float* W     = (const float*)d_in[4];
    const float* bias  = (const float*)d_in[5];
    float*       out   = (float*)d_out;

    const int* src = ei;
    const int* dst = ei + N_EDGES;

    cudaFuncSetAttribute(k_gemm, cudaFuncAttributeMaxDynamicSharedMemorySize,
                         SMEM_GEMM);

    cudaStream_t s2;
    cudaStreamCreateWithFlags(&s2, cudaStreamNonBlocking);
    cudaEvent_t evFork, evJoin;
    cudaEventCreateWithFlags(&evFork, cudaEventDisableTiming);
    cudaEventCreateWithFlags(&evJoin, cudaEventDisableTiming);

    void* counters_ptr = nullptr;
    cudaGetSymbolAddress(&counters_ptr, g_counters);
    cudaMemsetAsync(counters_ptr, 0, 2 * N_NODES * sizeof(int), 0);

    // fork: stream s2 runs LN + W conversion concurrent with the edge chain
    cudaEventRecord(evFork, 0);
    cudaStreamWaitEvent(s2, evFork, 0);
    k_layernorm<<<(N_NODES * 32 + 255) / 256, 256, 0, s2>>>(h, gamma, beta);
    k_convw<<<((D * 2 * D / 4) + 255) / 256, 256, 0, s2>>>(W);
    cudaEventRecord(evJoin, s2);

    // main stream: edge chain
    k_count<<<(N_EDGES + 255) / 256, 256>>>(src, dst);
    k_scan_local<<<SCAN_BLOCKS, 1024>>>();
    k_scan_block<<<1, 64>>>();
    k_fill_csr<<<(N_EDGES + 255) / 256, 256>>>(src, dst);

    // join, then aggregate + GEMM
    cudaStreamWaitEvent(0, evJoin, 0);
    k_aggregate<<<(N_NODES * 32 + 255) / 256, 256>>>();
    k_gemm<<<(N_NODES + GBM - 1) / GBM, 256, SMEM_GEMM>>>(bias, out);
}